// round 1
// baseline (speedup 1.0000x reference)
#include <cuda_runtime.h>
#include <math.h>

#define BB 64
#define SS 512
#define HH 768
#define LL 9

// scratch (no allocations allowed in kernel_launch)
__device__ int   g_src[BB * SS];   // g_src[b*SS + p] = source token s for compacted slot p
__device__ int   g_cnt[BB];        // number of valid tokens per row
__device__ float g_sb[LL];         // softmax(bias) for tail slots

// ---------------------------------------------------------------------------
// Kernel 1: per-row inclusive scan of valid_mask -> gather indices + counts.
// Also precomputes softmax(bias) once.
// ---------------------------------------------------------------------------
__global__ void __launch_bounds__(SS) ner_scan_kernel(const int* __restrict__ mask,
                                                      const float* __restrict__ bias) {
    __shared__ int sh[SS];
    const int b = blockIdx.x;
    const int s = threadIdx.x;
    const int m = mask[b * SS + s];
    sh[s] = m;
    __syncthreads();
    // Hillis-Steele inclusive scan
    for (int off = 1; off < SS; off <<= 1) {
        int v = (s >= off) ? sh[s - off] : 0;
        __syncthreads();
        sh[s] += v;
        __syncthreads();
    }
    const int incl = sh[s];
    if (m) g_src[b * SS + (incl - 1)] = s;
    if (s == SS - 1) g_cnt[b] = incl;

    if (b == 0 && s == 0) {
        float t[LL];
        float mx = -1e30f;
#pragma unroll
        for (int j = 0; j < LL; j++) { t[j] = bias[j]; mx = fmaxf(mx, t[j]); }
        float sum = 0.f;
#pragma unroll
        for (int j = 0; j < LL; j++) { t[j] = __expf(t[j] - mx); sum += t[j]; }
        const float inv = 1.f / sum;
#pragma unroll
        for (int j = 0; j < LL; j++) g_sb[j] = t[j] * inv;
    }
}

// ---------------------------------------------------------------------------
// Kernel 2: one warp handles 4 compacted slots of one batch row.
//   - valid slot p < cnt[b]: gather x[b, src(p)] (float4 coalesced), dot with
//     shared transposed W (LDS.128, conflict-free), + bias, softmax over L=9.
//   - tail slot p >= cnt[b]: write softmax(bias).
// Grid: 32768 slots / (4 slots/warp * 8 warps/block) = 1024 blocks x 256 thr.
// ---------------------------------------------------------------------------
__global__ void __launch_bounds__(256) ner_main_kernel(const float* __restrict__ X,
                                                       const float* __restrict__ W,
                                                       const float* __restrict__ bias,
                                                       float* __restrict__ out) {
    __shared__ float sWt[LL * HH];  // transposed: sWt[j*HH + k] = W[k*LL + j]
    const int tid = threadIdx.x;
    for (int idx = tid; idx < LL * HH; idx += 256) {
        const int k = idx / LL;
        const int j = idx - k * LL;
        sWt[j * HH + k] = W[idx];
    }
    __syncthreads();

    const int warp = (blockIdx.x * 256 + tid) >> 5;
    const int lane = tid & 31;
    const int t0   = warp * 4;           // first global slot index (b*SS + p)
    const int bi   = t0 >> 9;            // SS = 512
    const int p0   = t0 & (SS - 1);
    const int cnt  = g_cnt[bi];

    if (p0 >= cnt) {
        // all 4 slots are tail -> softmax(bias)
        if (lane < LL) {
            const float v = g_sb[lane];
#pragma unroll
            for (int i = 0; i < 4; i++)
                out[(size_t)(t0 + i) * LL + lane] = v;
        }
        return;
    }

    const int nv = min(4, cnt - p0);
    const float4* xp[4];
#pragma unroll
    for (int i = 0; i < 4; i++) {
        const int pi = p0 + ((i < nv) ? i : 0);  // clamp invalid to slot 0 (result discarded)
        const int s  = g_src[bi * SS + pi];
        xp[i] = (const float4*)(X + ((size_t)bi * SS + s) * HH);
    }

    float acc[4][LL];
#pragma unroll
    for (int i = 0; i < 4; i++)
#pragma unroll
        for (int j = 0; j < LL; j++) acc[i][j] = 0.f;

#pragma unroll
    for (int it = 0; it < HH / 128; it++) {   // 6 iterations, 128 floats per warp each
        const int k4 = it * 32 + lane;        // float4 index within the row
        const float4 x0 = xp[0][k4];
        const float4 x1 = xp[1][k4];
        const float4 x2 = xp[2][k4];
        const float4 x3 = xp[3][k4];
#pragma unroll
        for (int j = 0; j < LL; j++) {
            const float4 w = *(const float4*)(sWt + j * HH + k4 * 4);
            acc[0][j] += x0.x * w.x + x0.y * w.y + x0.z * w.z + x0.w * w.w;
            acc[1][j] += x1.x * w.x + x1.y * w.y + x1.z * w.z + x1.w * w.w;
            acc[2][j] += x2.x * w.x + x2.y * w.y + x2.z * w.z + x2.w * w.w;
            acc[3][j] += x3.x * w.x + x3.y * w.y + x3.z * w.z + x3.w * w.w;
        }
    }

    // full warp reduction -> every lane holds every sum
#pragma unroll
    for (int i = 0; i < 4; i++)
#pragma unroll
        for (int j = 0; j < LL; j++) {
            float v = acc[i][j];
            v += __shfl_xor_sync(0xffffffffu, v, 16);
            v += __shfl_xor_sync(0xffffffffu, v, 8);
            v += __shfl_xor_sync(0xffffffffu, v, 4);
            v += __shfl_xor_sync(0xffffffffu, v, 2);
            v += __shfl_xor_sync(0xffffffffu, v, 1);
            acc[i][j] = v;
        }

#pragma unroll
    for (int i = 0; i < 4; i++) {
        if (i < nv) {
            float l[LL];
            float mx = -1e30f;
#pragma unroll
            for (int j = 0; j < LL; j++) {
                l[j] = acc[i][j] + bias[j];
                mx = fmaxf(mx, l[j]);
            }
            float sum = 0.f;
#pragma unroll
            for (int j = 0; j < LL; j++) { l[j] = __expf(l[j] - mx); sum += l[j]; }
            const float inv = 1.f / sum;
            if (lane < LL)
                out[(size_t)(t0 + i) * LL + lane] = l[lane] * inv;
        } else {
            if (lane < LL)
                out[(size_t)(t0 + i) * LL + lane] = g_sb[lane];
        }
    }
}

// ---------------------------------------------------------------------------
extern "C" void kernel_launch(void* const* d_in, const int* in_sizes, int n_in,
                              void* d_out, int out_size) {
    const float* seq  = nullptr;  // [64,512,768] f32
    const int*   mask = nullptr;  // [64,512]     i32
    const float* W    = nullptr;  // [768,9]      f32
    const float* bias = nullptr;  // [9]          f32
    for (int i = 0; i < n_in; i++) {
        switch (in_sizes[i]) {
            case BB * SS * HH: seq  = (const float*)d_in[i]; break;
            case BB * SS:      mask = (const int*)d_in[i];   break;
            case HH * LL:      W    = (const float*)d_in[i]; break;
            case LL:           bias = (const float*)d_in[i]; break;
        }
    }
    float* out = (float*)d_out;

    ner_scan_kernel<<<BB, SS>>>(mask, bias);
    // 32768 slots total, 4 slots/warp, 8 warps/block -> 1024 blocks
    ner_main_kernel<<<(BB * SS) / (4 * 8), 256>>>(seq, W, bias, out);
}